// round 8
// baseline (speedup 1.0000x reference)
#include <cuda_runtime.h>
#include <math.h>

#define NIMG 89
#define NEG 0.2f

typedef unsigned long long u64;

#define FMA2(d,a,b,c) asm("fma.rn.f32x2 %0, %1, %2, %3;" : "=l"(d) : "l"(a), "l"(b), "l"(c))
__device__ __forceinline__ u64 pack2(float lo, float hi){
    u64 r; asm("mov.b64 %0, {%1,%2};" : "=l"(r) : "f"(lo), "f"(hi)); return r;
}

// ---------------- scratch ----------------
__device__ float g_conv1[NIMG*64*4096];
__device__ float g_pool1[NIMG*64*1024];
__device__ float g_conv2[NIMG*64*1024];
__device__ float g_pool2[NIMG*64*256];
__device__ float g_conv3[NIMG*64*256];
__device__ float g_a3   [NIMG*64*256];
__device__ float g_conv4[NIMG*64*256];
__device__ float g_feat [NIMG*64*256];
__device__ float g_q[NIMG*64*256];
__device__ float g_k[NIMG*64*256];
__device__ float g_v[NIMG*64*256];
__device__ float g_att[NIMG*64*256];
__device__ float g_mh [NIMG*64*256];
__device__ float g_y  [NIMG*64*256];
__device__ float g_scale[NIMG*64];
__device__ float g_sf[NIMG*2*256];
__device__ float g_sa[NIMG*256];
__device__ float g_stats[4*6*128];
__device__ float g_cmean[5*64];
__device__ float g_xc[5*64*1280];
__device__ float g_cov[5*64*64];
__device__ float g_qn[64*256*64];

__device__ __forceinline__ int group_of(int img){ return img < 64 ? 0 : 1 + (img-64)/5; }

// ---------------- conv1: 1->64, 64x64, pad 1 ----------------
__global__ void conv1_kernel(const float* __restrict__ in1, const float* __restrict__ in2,
                             const float* __restrict__ w){
    int img = blockIdx.x, ocb = blockIdx.y * 8;
    __shared__ float s_in[66*66];
    const float* src = (img < 64) ? in1 + img*4096 : in2 + (img-64)*4096;
    int tid = threadIdx.x;
    for(int p = tid; p < 66*66; p += 256){
        int y = p / 66, x = p % 66;
        float v = 0.f;
        if(y >= 1 && y <= 64 && x >= 1 && x <= 64) v = src[(y-1)*64 + (x-1)];
        s_in[p] = v;
    }
    float wr[8][9];
    #pragma unroll
    for(int o = 0; o < 8; o++)
        #pragma unroll
        for(int j = 0; j < 9; j++) wr[o][j] = w[(ocb+o)*9 + j];
    __syncthreads();
    for(int p = tid; p < 4096; p += 256){
        int y = p >> 6, x = p & 63;
        float in9[9];
        #pragma unroll
        for(int ky = 0; ky < 3; ky++)
            #pragma unroll
            for(int kx = 0; kx < 3; kx++) in9[ky*3+kx] = s_in[(y+ky)*66 + (x+kx)];
        #pragma unroll
        for(int o = 0; o < 8; o++){
            float a = 0.f;
            #pragma unroll
            for(int j = 0; j < 9; j++) a += wr[o][j]*in9[j];
            g_conv1[(img*64 + ocb + o)*4096 + p] = a;
        }
    }
}

// ---------------- BN statistics per (group, channel), fp32 + float4 ----------------
__global__ void bnstats_kernel(const float* __restrict__ src, int hw, int stage){
    int g = blockIdx.x / 64, c = blockIdx.x % 64;
    int start = (g == 0) ? 0 : 64 + (g-1)*5;
    int cnt   = (g == 0) ? 64 : 5;
    int tid = threadIdx.x;
    int N = cnt * hw;
    int hw4 = hw >> 2, N4 = N >> 2;
    float s = 0.f, s2 = 0.f;
    for(int idx = tid; idx < N4; idx += 256){
        int im = start + idx / hw4, p = (idx % hw4) << 2;
        float4 v = *(const float4*)&src[(size_t)(im*64 + c)*hw + p];
        s  += (v.x + v.y) + (v.z + v.w);
        s2 += v.x*v.x + v.y*v.y + v.z*v.z + v.w*v.w;
    }
    __shared__ float sh[256], sh2[256];
    sh[tid] = s; sh2[tid] = s2; __syncthreads();
    for(int o = 128; o > 0; o >>= 1){
        if(tid < o){ sh[tid] += sh[tid+o]; sh2[tid] += sh2[tid+o]; }
        __syncthreads();
    }
    if(tid == 0){
        double m = (double)sh[0] / N;
        double var = (double)sh2[0] / N - m*m;
        float* st = &g_stats[(stage*6 + g)*128 + c*2];
        st[0] = (float)m;
        st[1] = (float)(1.0 / sqrt(var + 1e-5));
    }
}

// ---------------- BN + LeakyReLU + 2x2 maxpool ----------------
__global__ void bn_pool_kernel(const float* __restrict__ src, float* __restrict__ dst,
                               int Ho, int stage,
                               const float* __restrict__ gamma, const float* __restrict__ beta){
    int total = NIMG*64*Ho*Ho;
    int idx = blockIdx.x*256 + threadIdx.x;
    if(idx >= total) return;
    int i = idx;
    int x = i % Ho; i /= Ho;
    int y = i % Ho; i /= Ho;
    int c = i % 64; int img = i / 64;
    int g = group_of(img);
    const float* st = &g_stats[(stage*6 + g)*128 + c*2];
    float m = st[0], r = st[1]*gamma[c], bb = beta[c];
    int Hi = Ho*2;
    const float* p = src + (size_t)(img*64 + c)*Hi*Hi;
    float best = -1e30f;
    #pragma unroll
    for(int dy = 0; dy < 2; dy++)
        #pragma unroll
        for(int dx = 0; dx < 2; dx++){
            float v = p[(2*y+dy)*Hi + 2*x+dx];
            v = (v - m)*r + bb;
            v = v >= 0.f ? v : NEG*v;
            best = fmaxf(best, v);
        }
    dst[idx] = best;
}

// ---------------- BN + LeakyReLU ----------------
__global__ void bn_act_kernel(const float* __restrict__ src, float* __restrict__ dst,
                              int hw, int stage,
                              const float* __restrict__ gamma, const float* __restrict__ beta){
    int total = NIMG*64*hw;
    int idx = blockIdx.x*256 + threadIdx.x;
    if(idx >= total) return;
    int c = (idx / hw) % 64;
    int img = idx / (hw*64);
    int g = group_of(img);
    const float* st = &g_stats[(stage*6 + g)*128 + c*2];
    float v = (src[idx] - st[0])*st[1]*gamma[c] + beta[c];
    dst[idx] = v >= 0.f ? v : NEG*v;
}

// ---------------- 64->64 3x3 conv, f32x2 packed FMA ----------------
// Block: IPB images x OC output channels. Threads = IPB*(H*H/4); each thread
// owns 4 consecutive pixels in a row (2 f32x2 pairs).
// Padded smem tile: left pad 2 (for 8B-aligned float2 loads), right pad 2,
// 1 row top/bottom; stride = H+4 (even), rows = H+2. Borders zeroed once.
template<int H, int OC, int IPB>
__global__ void conv64v2_kernel(const float* __restrict__ src, const float* __restrict__ w,
                                float* __restrict__ dst){
    constexpr int HW = H*H;
    constexpr int PSTR = H+4;
    constexpr int TILE = (H+2)*PSTR;
    constexpr int TPI = HW/4;
    constexpr int THREADS = IPB*TPI;
    constexpr int LPT = IPB*HW/THREADS;   // = 4
    extern __shared__ float smem[];
    u64*   s_w2 = (u64*)smem;             // OC*64*9 duplicated weights
    float* s_in = smem + OC*64*9*2;       // 2 * IPB*TILE

    int tid = threadIdx.x;
    int ocb = blockIdx.y * OC;
    int img0 = blockIdx.x * IPB;

    // duplicated weights into smem
    for(int p = tid; p < OC*64*9; p += THREADS){
        float wv = w[(size_t)ocb*576 + p];
        ((float2*)s_w2)[p] = make_float2(wv, wv);
    }
    // zero input buffers (borders stay zero forever)
    for(int p = tid; p < 2*IPB*TILE; p += THREADS) s_in[p] = 0.f;
    __syncthreads();

    int il = tid / TPI;
    int tl = tid % TPI;
    constexpr int XG = H/4;
    int row = tl / XG, x0 = 4*(tl % XG);
    int img = img0 + il;
    bool valid = (img < NIMG);
    const float* ibase = src + (size_t)img0*64*HW;

    // preload ic 0
    #pragma unroll
    for(int k = 0; k < LPT; k++){
        int idx = tid + k*THREADS;
        int im = idx / HW, p = idx % HW;
        float v = (img0 + im < NIMG) ? ibase[(size_t)im*64*HW + p] : 0.f;
        s_in[im*TILE + (1 + p/H)*PSTR + 2 + p%H] = v;
    }
    __syncthreads();

    u64 acc[OC][2];
    #pragma unroll
    for(int o = 0; o < OC; o++){ acc[o][0] = 0ull; acc[o][1] = 0ull; }

    for(int ic = 0; ic < 64; ic++){
        int buf = ic & 1;
        if(ic < 63){
            #pragma unroll
            for(int k = 0; k < LPT; k++){
                int idx = tid + k*THREADS;
                int im = idx / HW, p = idx % HW;
                float v = (img0 + im < NIMG) ? ibase[(size_t)im*64*HW + (ic+1)*HW + p] : 0.f;
                s_in[(buf^1)*IPB*TILE + im*TILE + (1 + p/H)*PSTR + 2 + p%H] = v;
            }
        }
        // gather: padded col of input col c is c+2; A starts at input col x0-2 -> padded x0
        const float* tp = s_in + buf*IPB*TILE + il*TILE + row*PSTR + x0;
        u64 in2[3][3][2];
        #pragma unroll
        for(int ky = 0; ky < 3; ky++){
            const float2* rp = (const float2*)(tp + ky*PSTR);
            float2 A = rp[0], B = rp[1], C = rp[2], D = rp[3];
            u64 p00 = pack2(A.y, B.x);   // kx=0: {x-1, x}
            u64 p01 = pack2(B.y, C.x);   // kx=0 pair1 / kx=2 pair0: {x+1, x+2}
            u64 pB  = pack2(B.x, B.y);   // kx=1 pair0
            u64 pC  = pack2(C.x, C.y);   // kx=1 pair1
            u64 p21 = pack2(C.y, D.x);   // kx=2 pair1: {x+3, x+4}
            in2[ky][0][0] = p00; in2[ky][0][1] = p01;
            in2[ky][1][0] = pB;  in2[ky][1][1] = pC;
            in2[ky][2][0] = p01; in2[ky][2][1] = p21;
        }
        const u64* wic = s_w2 + ic*9;
        #pragma unroll
        for(int o = 0; o < OC; o++){
            const u64* wrow = wic + o*576;
            #pragma unroll
            for(int ky = 0; ky < 3; ky++)
                #pragma unroll
                for(int kx = 0; kx < 3; kx++){
                    u64 wv = wrow[ky*3 + kx];
                    FMA2(acc[o][0], wv, in2[ky][kx][0], acc[o][0]);
                    FMA2(acc[o][1], wv, in2[ky][kx][1], acc[o][1]);
                }
        }
        __syncthreads();
    }

    if(valid){
        float* dp = dst + (size_t)(img*64 + ocb)*HW + row*H + x0;
        #pragma unroll
        for(int o = 0; o < OC; o++){
            float4 v;
            asm("mov.b64 {%0,%1}, %2;" : "=f"(v.x), "=f"(v.y) : "l"(acc[o][0]));
            asm("mov.b64 {%0,%1}, %2;" : "=f"(v.z), "=f"(v.w) : "l"(acc[o][1]));
            *(float4*)(dp + (size_t)o*HW) = v;
        }
    }
}

// ---------------- QKV projection ----------------
__global__ void qkv_kernel(const float* __restrict__ wq, const float* __restrict__ bq,
                           const float* __restrict__ wk, const float* __restrict__ bk,
                           const float* __restrict__ wv, const float* __restrict__ bv){
    int b = blockIdx.x;
    int m = blockIdx.y / 4;
    int ot = (blockIdx.y % 4) * 16;
    const float* W  = (m == 0) ? wq : (m == 1 ? wk : wv);
    const float* Bb = (m == 0) ? bq : (m == 1 ? bk : bv);
    float* dst = (m == 0) ? g_q : (m == 1 ? g_k : g_v);
    __shared__ float s_w[16*64];
    int tid = threadIdx.x;
    for(int p = tid; p < 1024; p += 256) s_w[p] = W[(ot + p/64)*64 + p%64];
    __syncthreads();
    int i = tid;
    float acc[16];
    #pragma unroll
    for(int o = 0; o < 16; o++) acc[o] = Bb[ot + o];
    const float* xb = g_feat + (size_t)b*16384;
    for(int c = 0; c < 64; c++){
        float xv = xb[c*256 + i];
        #pragma unroll
        for(int o = 0; o < 16; o++) acc[o] += s_w[o*64 + c]*xv;
    }
    #pragma unroll
    for(int o = 0; o < 16; o++) dst[(size_t)b*16384 + (ot+o)*256 + i] = acc[o];
}

// ---------------- attention ----------------
__global__ void attn_kernel(const float* __restrict__ rel_h, const float* __restrict__ rel_w){
    int b = blockIdx.x, h = blockIdx.y;
    __shared__ float s_q[16*256];
    __shared__ float s_k[16*256];
    __shared__ float s_v[16*256];
    int tid = threadIdx.x;
    const size_t base = (size_t)b*16384 + h*4096;
    for(int p = tid; p < 4096; p += 256){
        s_q[p] = g_q[base + p];
        s_k[p] = g_k[base + p];
        s_v[p] = g_v[base + p];
    }
    __syncthreads();
    int warp = tid / 32, lane = tid % 32;
    for(int r = 0; r < 32; r++){
        int i = warp*32 + r;
        int a = i / 16, bcol = i % 16;
        float qi[16], pi[16];
        #pragma unroll
        for(int d = 0; d < 16; d++){
            qi[d] = s_q[d*256 + i];
            pi[d] = rel_h[(h*16 + d)*16 + bcol] + rel_w[(h*16 + d)*16 + a];
        }
        float sc[8];
        #pragma unroll
        for(int jj = 0; jj < 8; jj++){
            int j = lane + jj*32;
            float s = 0.f;
            #pragma unroll
            for(int d = 0; d < 16; d++)
                s += qi[d]*s_k[d*256 + j] + pi[d]*s_q[d*256 + j];
            sc[jj] = s;
        }
        float mx = sc[0];
        #pragma unroll
        for(int jj = 1; jj < 8; jj++) mx = fmaxf(mx, sc[jj]);
        #pragma unroll
        for(int o = 16; o > 0; o >>= 1) mx = fmaxf(mx, __shfl_xor_sync(0xffffffffu, mx, o));
        float sum = 0.f;
        #pragma unroll
        for(int jj = 0; jj < 8; jj++){ sc[jj] = __expf(sc[jj] - mx); sum += sc[jj]; }
        #pragma unroll
        for(int o = 16; o > 0; o >>= 1) sum += __shfl_xor_sync(0xffffffffu, sum, o);
        float inv = 1.f / sum;
        #pragma unroll
        for(int d = 0; d < 16; d++){
            float pv = 0.f;
            #pragma unroll
            for(int jj = 0; jj < 8; jj++) pv += s_v[d*256 + lane + jj*32]*sc[jj];
            #pragma unroll
            for(int o = 16; o > 0; o >>= 1) pv += __shfl_xor_sync(0xffffffffu, pv, o);
            if(lane == 0) g_att[base + d*256 + i] = pv*inv;
        }
    }
}

// ---------------- per-sample LayerNorm + residual (fp32) ----------------
__global__ void ln_kernel(const float* __restrict__ ln_g, const float* __restrict__ ln_b){
    int b = blockIdx.x, tid = threadIdx.x;
    const float* src = g_att + (size_t)b*16384;
    float s = 0.f, s2 = 0.f;
    for(int p = tid; p < 4096; p += 256){
        float4 v = *(const float4*)&src[p*4];
        s  += (v.x + v.y) + (v.z + v.w);
        s2 += v.x*v.x + v.y*v.y + v.z*v.z + v.w*v.w;
    }
    __shared__ float sh[256], sh2[256];
    sh[tid] = s; sh2[tid] = s2; __syncthreads();
    for(int o = 128; o > 0; o >>= 1){
        if(tid < o){ sh[tid] += sh[tid+o]; sh2[tid] += sh2[tid+o]; }
        __syncthreads();
    }
    __shared__ float m_s, r_s;
    if(tid == 0){
        double m = (double)sh[0]/16384.0;
        double var = (double)sh2[0]/16384.0 - m*m;
        m_s = (float)m;
        r_s = (float)(1.0/sqrt(var + 1e-5));
    }
    __syncthreads();
    float m = m_s, r = r_s;
    for(int p = tid; p < 16384; p += 256){
        g_mh[(size_t)b*16384 + p] = (src[p] - m)*r*ln_g[p] + ln_b[p] + g_feat[(size_t)b*16384 + p];
    }
}

// ---------------- CBAM channel attention ----------------
__global__ void ca_kernel(const float* __restrict__ w1, const float* __restrict__ b1,
                          const float* __restrict__ w2, const float* __restrict__ b2){
    int b = blockIdx.x, tid = threadIdx.x;
    __shared__ float s_sum[256], s_max[256];
    int c = tid / 4, qp = tid % 4;
    const float* p = g_feat + (size_t)(b*64 + c)*256 + qp*64;
    float s = 0.f, mx = -1e30f;
    for(int i = 0; i < 64; i++){ float v = p[i]; s += v; mx = fmaxf(mx, v); }
    s_sum[tid] = s; s_max[tid] = mx;
    __syncthreads();
    __shared__ float avg[64], mxc[64];
    if(tid < 64){
        float ss = 0.f, mm = -1e30f;
        for(int q = 0; q < 4; q++){ ss += s_sum[tid*4+q]; mm = fmaxf(mm, s_max[tid*4+q]); }
        avg[tid] = ss/256.f; mxc[tid] = mm;
    }
    __syncthreads();
    __shared__ float hA[4], hM[4];
    if(tid < 8){
        int hh = tid % 4; bool isA = tid < 4;
        const float* f = isA ? avg : mxc;
        float a = b1[hh];
        for(int cc = 0; cc < 64; cc++) a += w1[hh*64 + cc]*f[cc];
        a = fmaxf(a, 0.f);
        if(isA) hA[hh] = a; else hM[hh] = a;
    }
    __syncthreads();
    if(tid < 64){
        float sv = 2.f*b2[tid];
        for(int hh = 0; hh < 4; hh++) sv += w2[tid*4 + hh]*(hA[hh] + hM[hh]);
        g_scale[b*64 + tid] = 1.f/(1.f + __expf(-sv));
    }
}

// ---------------- CBAM spatial features ----------------
__global__ void sf_kernel(){
    int b = blockIdx.x, i = threadIdx.x;
    float s = 0.f, mx = -1e30f;
    for(int c = 0; c < 64; c++){
        float v = g_scale[b*64 + c]*g_feat[(size_t)b*16384 + c*256 + i];
        s += v; mx = fmaxf(mx, v);
    }
    g_sf[b*512 + i] = s/64.f;
    g_sf[b*512 + 256 + i] = mx;
}

// ---------------- 7x7 spatial attention conv + sigmoid ----------------
__global__ void saconv_kernel(const float* __restrict__ sw, const float* __restrict__ sb){
    int b = blockIdx.x, i = threadIdx.x;
    int y = i/16, x = i%16;
    float a = sb[0];
    for(int ch = 0; ch < 2; ch++)
        for(int ky = 0; ky < 7; ky++){
            int yy = y + ky - 3; if(yy < 0 || yy >= 16) continue;
            for(int kx = 0; kx < 7; kx++){
                int xx = x + kx - 3; if(xx < 0 || xx >= 16) continue;
                a += sw[ch*49 + ky*7 + kx]*g_sf[b*512 + ch*256 + yy*16 + xx];
            }
        }
    g_sa[b*256 + i] = 1.f/(1.f + __expf(-a));
}

// ---------------- final combine ----------------
__global__ void comb_kernel(){
    int idx = blockIdx.x*256 + threadIdx.x;
    if(idx >= NIMG*16384) return;
    int b = idx/16384, rr = idx%16384, c = rr/256, i = rr%256;
    float xv = g_feat[idx];
    g_y[idx] = g_mh[idx] + g_sa[b*256 + i]*g_scale[b*64 + c]*xv + xv;
}

// ---------------- covariance pipeline ----------------
__global__ void cmean_kernel(){
    int n = blockIdx.x/64, c = blockIdx.x%64, tid = threadIdx.x;
    float s = 0.f;
    for(int m = tid; m < 1280; m += 256){
        int im = 64 + n*5 + m/256, i = m%256;
        s += g_y[(size_t)(im*64 + c)*256 + i];
    }
    __shared__ float sh[256];
    sh[tid] = s; __syncthreads();
    for(int o = 128; o > 0; o >>= 1){ if(tid < o) sh[tid] += sh[tid+o]; __syncthreads(); }
    if(tid == 0) g_cmean[n*64 + c] = sh[0]/1280.f;
}

__global__ void xc_kernel(){
    int idx = blockIdx.x*256 + threadIdx.x;
    if(idx >= 5*64*1280) return;
    int n = idx/(64*1280), rr = idx%(64*1280), c = rr/1280, m = rr%1280;
    int im = 64 + n*5 + m/256, i = m%256;
    g_xc[idx] = g_y[(size_t)(im*64 + c)*256 + i] - g_cmean[n*64 + c];
}

__global__ void cov_kernel(){
    int n = blockIdx.x;
    int pid = blockIdx.y*256 + threadIdx.x;
    int c = pid/64, d = pid%64;
    const float4* a  = (const float4*)(g_xc + (size_t)(n*64 + c)*1280);
    const float4* bb = (const float4*)(g_xc + (size_t)(n*64 + d)*1280);
    float s = 0.f;
    #pragma unroll 4
    for(int m = 0; m < 320; m++){
        float4 av = a[m], bv = bb[m];
        s += av.x*bv.x + av.y*bv.y + av.z*bv.z + av.w*bv.w;
    }
    g_cov[n*4096 + pid] = s/1279.f;
}

// ---------------- query normalization + transpose ----------------
__global__ void qn_kernel(){
    int b = blockIdx.x, tid = threadIdx.x;
    __shared__ float part[256];
    __shared__ float rn[64];
    int c = tid/4, qp = tid%4;
    const float* p = g_y + (size_t)(b*64 + c)*256 + qp*64;
    float s = 0.f;
    for(int i = 0; i < 64; i++) s += p[i]*p[i];
    part[tid] = s; __syncthreads();
    if(tid < 64){
        float t = part[tid*4] + part[tid*4+1] + part[tid*4+2] + part[tid*4+3];
        rn[tid] = 1.f/sqrtf(t);
    }
    __syncthreads();
    for(int p2 = tid; p2 < 16384; p2 += 256){
        int c2 = p2/256, i = p2%256;
        g_qn[(size_t)(b*256 + i)*64 + c2] = g_y[(size_t)(b*64 + c2)*256 + i]*rn[c2];
    }
}

// ---------------- sim quadratic form + classifier ----------------
__global__ void sim_kernel(const float* __restrict__ cls_w, float* __restrict__ out){
    int b = blockIdx.x, j = blockIdx.y;
    __shared__ float s_cov[4096];
    int tid = threadIdx.x;
    for(int p = tid; p < 4096; p += 256) s_cov[p] = g_cov[j*4096 + p];
    __syncthreads();
    float v[64];
    const float4* vp = (const float4*)(g_qn + (size_t)(b*256 + tid)*64);
    #pragma unroll
    for(int c4 = 0; c4 < 16; c4++){
        float4 f = vp[c4];
        v[c4*4] = f.x; v[c4*4+1] = f.y; v[c4*4+2] = f.z; v[c4*4+3] = f.w;
    }
    float quad = 0.f;
    for(int c = 0; c < 64; c++){
        float t = 0.f;
        #pragma unroll 8
        for(int d = 0; d < 64; d++) t += s_cov[c*64 + d]*v[d];
        quad += v[c]*t;
    }
    float val = quad >= 0.f ? quad : NEG*quad;
    val *= cls_w[tid];
    __shared__ float red[256];
    red[tid] = val; __syncthreads();
    for(int o = 128; o > 0; o >>= 1){ if(tid < o) red[tid] += red[tid+o]; __syncthreads(); }
    if(tid == 0) out[b*5 + j] = red[0];
}

// ---------------- host orchestration ----------------
extern "C" void kernel_launch(void* const* d_in, const int* in_sizes, int n_in,
                              void* d_out, int out_size){
    const float* input1  = (const float*)d_in[0];
    const float* input2  = (const float*)d_in[1];
    const float* conv1_w = (const float*)d_in[2];
    const float* bn1_g = (const float*)d_in[3];  const float* bn1_b = (const float*)d_in[4];
    const float* conv2_w = (const float*)d_in[5];
    const float* bn2_g = (const float*)d_in[6];  const float* bn2_b = (const float*)d_in[7];
    const float* conv3_w = (const float*)d_in[8];
    const float* bn3_g = (const float*)d_in[9];  const float* bn3_b = (const float*)d_in[10];
    const float* conv4_w = (const float*)d_in[11];
    const float* bn4_g = (const float*)d_in[12]; const float* bn4_b = (const float*)d_in[13];
    const float* wq = (const float*)d_in[14]; const float* bq = (const float*)d_in[15];
    const float* wk = (const float*)d_in[16]; const float* bk = (const float*)d_in[17];
    const float* wv = (const float*)d_in[18]; const float* bv = (const float*)d_in[19];
    const float* rel_h = (const float*)d_in[20]; const float* rel_w = (const float*)d_in[21];
    const float* ln_g = (const float*)d_in[22];  const float* ln_b = (const float*)d_in[23];
    const float* ca_w1 = (const float*)d_in[24]; const float* ca_b1 = (const float*)d_in[25];
    const float* ca_w2 = (const float*)d_in[26]; const float* ca_b2 = (const float*)d_in[27];
    const float* sa_w = (const float*)d_in[28];  const float* sa_b = (const float*)d_in[29];
    const float* cls_w = (const float*)d_in[30];
    float* out = (float*)d_out;

    float *p_conv1, *p_pool1, *p_conv2, *p_pool2, *p_conv3, *p_a3, *p_conv4, *p_feat;
    cudaGetSymbolAddress((void**)&p_conv1, g_conv1);
    cudaGetSymbolAddress((void**)&p_pool1, g_pool1);
    cudaGetSymbolAddress((void**)&p_conv2, g_conv2);
    cudaGetSymbolAddress((void**)&p_pool2, g_pool2);
    cudaGetSymbolAddress((void**)&p_conv3, g_conv3);
    cudaGetSymbolAddress((void**)&p_a3,    g_a3);
    cudaGetSymbolAddress((void**)&p_conv4, g_conv4);
    cudaGetSymbolAddress((void**)&p_feat,  g_feat);

    // conv64 smem sizes
    const int smem32 = 16*64*9*8 + 2*1*(34*36)*4;   // 73728 + 9792 = 83520
    const int smem16 = 8*64*9*8 + 2*2*(18*20)*4;    // 36864 + 5760 = 42624
    cudaFuncSetAttribute((const void*)conv64v2_kernel<32,16,1>,
                         cudaFuncAttributeMaxDynamicSharedMemorySize, smem32);
    cudaFuncSetAttribute((const void*)conv64v2_kernel<16,8,2>,
                         cudaFuncAttributeMaxDynamicSharedMemorySize, smem16);

    // features
    conv1_kernel<<<dim3(NIMG,8),256>>>(input1, input2, conv1_w);
    bnstats_kernel<<<384,256>>>(p_conv1, 4096, 0);
    bn_pool_kernel<<<(NIMG*64*1024+255)/256,256>>>(p_conv1, p_pool1, 32, 0, bn1_g, bn1_b);

    conv64v2_kernel<32,16,1><<<dim3(NIMG,4),256,smem32>>>(p_pool1, conv2_w, p_conv2);
    bnstats_kernel<<<384,256>>>(p_conv2, 1024, 1);
    bn_pool_kernel<<<(NIMG*64*256+255)/256,256>>>(p_conv2, p_pool2, 16, 1, bn2_g, bn2_b);

    conv64v2_kernel<16,8,2><<<dim3((NIMG+1)/2,8),128,smem16>>>(p_pool2, conv3_w, p_conv3);
    bnstats_kernel<<<384,256>>>(p_conv3, 256, 2);
    bn_act_kernel<<<(NIMG*64*256+255)/256,256>>>(p_conv3, p_a3, 256, 2, bn3_g, bn3_b);

    conv64v2_kernel<16,8,2><<<dim3((NIMG+1)/2,8),128,smem16>>>(p_a3, conv4_w, p_conv4);
    bnstats_kernel<<<384,256>>>(p_conv4, 256, 3);
    bn_act_kernel<<<(NIMG*64*256+255)/256,256>>>(p_conv4, p_feat, 256, 3, bn4_g, bn4_b);

    // sa_module
    qkv_kernel<<<dim3(NIMG,12),256>>>(wq, bq, wk, bk, wv, bv);
    attn_kernel<<<dim3(NIMG,4),256>>>(rel_h, rel_w);
    ln_kernel<<<NIMG,256>>>(ln_g, ln_b);
    ca_kernel<<<NIMG,256>>>(ca_w1, ca_b1, ca_w2, ca_b2);
    sf_kernel<<<NIMG,256>>>();
    saconv_kernel<<<NIMG,256>>>(sa_w, sa_b);
    comb_kernel<<<(NIMG*16384+255)/256,256>>>();

    // covariance + similarity
    cmean_kernel<<<320,256>>>();
    xc_kernel<<<(5*64*1280+255)/256,256>>>();
    cov_kernel<<<dim3(5,16),256>>>();
    qn_kernel<<<64,256>>>();
    sim_kernel<<<dim3(64,5),256>>>(cls_w, out);
}

// round 9
// speedup vs baseline: 1.0189x; 1.0189x over previous
#include <cuda_runtime.h>
#include <math.h>

#define NIMG 89
#define NEG 0.2f

typedef unsigned long long u64;

#define FMA2(d,a,b,c) asm("fma.rn.f32x2 %0, %1, %2, %3;" : "=l"(d) : "l"(a), "l"(b), "l"(c))
__device__ __forceinline__ u64 pack2(float lo, float hi){
    u64 r; asm("mov.b64 %0, {%1,%2};" : "=l"(r) : "f"(lo), "f"(hi)); return r;
}

// ---------------- scratch ----------------
__device__ float g_conv1[NIMG*64*4096];
__device__ float g_pool1[NIMG*64*1024];
__device__ float g_conv2[NIMG*64*1024];
__device__ float g_pool2[NIMG*64*256];
__device__ float g_conv3[NIMG*64*256];
__device__ float g_a3   [NIMG*64*256];
__device__ float g_conv4[NIMG*64*256];
__device__ float g_feat [NIMG*64*256];
__device__ float g_q[NIMG*64*256];
__device__ float g_k[NIMG*64*256];
__device__ float g_v[NIMG*64*256];
__device__ float g_att[NIMG*64*256];
__device__ float g_mh [NIMG*64*256];
__device__ float g_y  [NIMG*64*256];
__device__ float g_scale[NIMG*64];
__device__ float g_sf[NIMG*2*256];
__device__ float g_sa[NIMG*256];
__device__ float g_stats[4*6*128];
__device__ float g_cmean[5*64];
__device__ float g_xc[5*64*1280];
__device__ float g_cov[5*64*64];
__device__ float g_qn[64*256*64];

__device__ __forceinline__ int group_of(int img){ return img < 64 ? 0 : 1 + (img-64)/5; }

// ---------------- conv1: 1->64, 64x64, pad 1 ----------------
__global__ void conv1_kernel(const float* __restrict__ in1, const float* __restrict__ in2,
                             const float* __restrict__ w){
    int img = blockIdx.x, ocb = blockIdx.y * 8;
    __shared__ float s_in[66*66];
    const float* src = (img < 64) ? in1 + img*4096 : in2 + (img-64)*4096;
    int tid = threadIdx.x;
    for(int p = tid; p < 66*66; p += 256){
        int y = p / 66, x = p % 66;
        float v = 0.f;
        if(y >= 1 && y <= 64 && x >= 1 && x <= 64) v = src[(y-1)*64 + (x-1)];
        s_in[p] = v;
    }
    float wr[8][9];
    #pragma unroll
    for(int o = 0; o < 8; o++)
        #pragma unroll
        for(int j = 0; j < 9; j++) wr[o][j] = w[(ocb+o)*9 + j];
    __syncthreads();
    for(int p = tid; p < 4096; p += 256){
        int y = p >> 6, x = p & 63;
        float in9[9];
        #pragma unroll
        for(int ky = 0; ky < 3; ky++)
            #pragma unroll
            for(int kx = 0; kx < 3; kx++) in9[ky*3+kx] = s_in[(y+ky)*66 + (x+kx)];
        #pragma unroll
        for(int o = 0; o < 8; o++){
            float a = 0.f;
            #pragma unroll
            for(int j = 0; j < 9; j++) a += wr[o][j]*in9[j];
            g_conv1[(img*64 + ocb + o)*4096 + p] = a;
        }
    }
}

// ---------------- BN statistics per (group, channel), fp32 + float4 ----------------
__global__ void bnstats_kernel(const float* __restrict__ src, int hw, int stage){
    int g = blockIdx.x / 64, c = blockIdx.x % 64;
    int start = (g == 0) ? 0 : 64 + (g-1)*5;
    int cnt   = (g == 0) ? 64 : 5;
    int tid = threadIdx.x;
    int N = cnt * hw;
    int hw4 = hw >> 2, N4 = N >> 2;
    float s = 0.f, s2 = 0.f;
    for(int idx = tid; idx < N4; idx += 256){
        int im = start + idx / hw4, p = (idx % hw4) << 2;
        float4 v = *(const float4*)&src[(size_t)(im*64 + c)*hw + p];
        s  += (v.x + v.y) + (v.z + v.w);
        s2 += v.x*v.x + v.y*v.y + v.z*v.z + v.w*v.w;
    }
    __shared__ float sh[256], sh2[256];
    sh[tid] = s; sh2[tid] = s2; __syncthreads();
    for(int o = 128; o > 0; o >>= 1){
        if(tid < o){ sh[tid] += sh[tid+o]; sh2[tid] += sh2[tid+o]; }
        __syncthreads();
    }
    if(tid == 0){
        double m = (double)sh[0] / N;
        double var = (double)sh2[0] / N - m*m;
        float* st = &g_stats[(stage*6 + g)*128 + c*2];
        st[0] = (float)m;
        st[1] = (float)(1.0 / sqrt(var + 1e-5));
    }
}

// ---------------- BN + LeakyReLU + 2x2 maxpool ----------------
__global__ void bn_pool_kernel(const float* __restrict__ src, float* __restrict__ dst,
                               int Ho, int stage,
                               const float* __restrict__ gamma, const float* __restrict__ beta){
    int total = NIMG*64*Ho*Ho;
    int idx = blockIdx.x*256 + threadIdx.x;
    if(idx >= total) return;
    int i = idx;
    int x = i % Ho; i /= Ho;
    int y = i % Ho; i /= Ho;
    int c = i % 64; int img = i / 64;
    int g = group_of(img);
    const float* st = &g_stats[(stage*6 + g)*128 + c*2];
    float m = st[0], r = st[1]*gamma[c], bb = beta[c];
    int Hi = Ho*2;
    const float* p = src + (size_t)(img*64 + c)*Hi*Hi;
    float best = -1e30f;
    #pragma unroll
    for(int dy = 0; dy < 2; dy++)
        #pragma unroll
        for(int dx = 0; dx < 2; dx++){
            float v = p[(2*y+dy)*Hi + 2*x+dx];
            v = (v - m)*r + bb;
            v = v >= 0.f ? v : NEG*v;
            best = fmaxf(best, v);
        }
    dst[idx] = best;
}

// ---------------- BN + LeakyReLU ----------------
__global__ void bn_act_kernel(const float* __restrict__ src, float* __restrict__ dst,
                              int hw, int stage,
                              const float* __restrict__ gamma, const float* __restrict__ beta){
    int total = NIMG*64*hw;
    int idx = blockIdx.x*256 + threadIdx.x;
    if(idx >= total) return;
    int c = (idx / hw) % 64;
    int img = idx / (hw*64);
    int g = group_of(img);
    const float* st = &g_stats[(stage*6 + g)*128 + c*2];
    float v = (src[idx] - st[0])*st[1]*gamma[c] + beta[c];
    dst[idx] = v >= 0.f ? v : NEG*v;
}

// ---------------- 64->64 3x3 conv, f32x2 packed FMA ----------------
// Block: IPB images x OC output channels. Threads = IPB*(H*H/4); each thread
// owns 4 consecutive pixels in a row (2 f32x2 pairs).
// Padded smem tile: left pad 2 (for 8B-aligned float2 loads), right pad 2,
// 1 row top/bottom; stride = H+4 (even), rows = H+2. Borders zeroed once.
template<int H, int OC, int IPB>
__global__ void conv64v2_kernel(const float* __restrict__ src, const float* __restrict__ w,
                                float* __restrict__ dst){
    constexpr int HW = H*H;
    constexpr int PSTR = H+4;
    constexpr int TILE = (H+2)*PSTR;
    constexpr int TPI = HW/4;
    constexpr int THREADS = IPB*TPI;
    constexpr int LPT = IPB*HW/THREADS;   // = 4
    extern __shared__ float smem[];
    u64*   s_w2 = (u64*)smem;             // OC*64*9 duplicated weights
    float* s_in = smem + OC*64*9*2;       // 2 * IPB*TILE

    int tid = threadIdx.x;
    int ocb = blockIdx.y * OC;
    int img0 = blockIdx.x * IPB;

    // duplicated weights into smem
    for(int p = tid; p < OC*64*9; p += THREADS){
        float wv = w[(size_t)ocb*576 + p];
        ((float2*)s_w2)[p] = make_float2(wv, wv);
    }
    // zero input buffers (borders stay zero forever)
    for(int p = tid; p < 2*IPB*TILE; p += THREADS) s_in[p] = 0.f;
    __syncthreads();

    int il = tid / TPI;
    int tl = tid % TPI;
    constexpr int XG = H/4;
    int row = tl / XG, x0 = 4*(tl % XG);
    int img = img0 + il;
    bool valid = (img < NIMG);
    const float* ibase = src + (size_t)img0*64*HW;

    // preload ic 0
    #pragma unroll
    for(int k = 0; k < LPT; k++){
        int idx = tid + k*THREADS;
        int im = idx / HW, p = idx % HW;
        float v = (img0 + im < NIMG) ? ibase[(size_t)im*64*HW + p] : 0.f;
        s_in[im*TILE + (1 + p/H)*PSTR + 2 + p%H] = v;
    }
    __syncthreads();

    u64 acc[OC][2];
    #pragma unroll
    for(int o = 0; o < OC; o++){ acc[o][0] = 0ull; acc[o][1] = 0ull; }

    for(int ic = 0; ic < 64; ic++){
        int buf = ic & 1;
        if(ic < 63){
            #pragma unroll
            for(int k = 0; k < LPT; k++){
                int idx = tid + k*THREADS;
                int im = idx / HW, p = idx % HW;
                float v = (img0 + im < NIMG) ? ibase[(size_t)im*64*HW + (ic+1)*HW + p] : 0.f;
                s_in[(buf^1)*IPB*TILE + im*TILE + (1 + p/H)*PSTR + 2 + p%H] = v;
            }
        }
        // gather: padded col of input col c is c+2; A starts at input col x0-2 -> padded x0
        const float* tp = s_in + buf*IPB*TILE + il*TILE + row*PSTR + x0;
        u64 in2[3][3][2];
        #pragma unroll
        for(int ky = 0; ky < 3; ky++){
            const float2* rp = (const float2*)(tp + ky*PSTR);
            float2 A = rp[0], B = rp[1], C = rp[2], D = rp[3];
            u64 p00 = pack2(A.y, B.x);   // kx=0: {x-1, x}
            u64 p01 = pack2(B.y, C.x);   // kx=0 pair1 / kx=2 pair0: {x+1, x+2}
            u64 pB  = pack2(B.x, B.y);   // kx=1 pair0
            u64 pC  = pack2(C.x, C.y);   // kx=1 pair1
            u64 p21 = pack2(C.y, D.x);   // kx=2 pair1: {x+3, x+4}
            in2[ky][0][0] = p00; in2[ky][0][1] = p01;
            in2[ky][1][0] = pB;  in2[ky][1][1] = pC;
            in2[ky][2][0] = p01; in2[ky][2][1] = p21;
        }
        const u64* wic = s_w2 + ic*9;
        #pragma unroll
        for(int o = 0; o < OC; o++){
            const u64* wrow = wic + o*576;
            #pragma unroll
            for(int ky = 0; ky < 3; ky++)
                #pragma unroll
                for(int kx = 0; kx < 3; kx++){
                    u64 wv = wrow[ky*3 + kx];
                    FMA2(acc[o][0], wv, in2[ky][kx][0], acc[o][0]);
                    FMA2(acc[o][1], wv, in2[ky][kx][1], acc[o][1]);
                }
        }
        __syncthreads();
    }

    if(valid){
        float* dp = dst + (size_t)(img*64 + ocb)*HW + row*H + x0;
        #pragma unroll
        for(int o = 0; o < OC; o++){
            float4 v;
            asm("mov.b64 {%0,%1}, %2;" : "=f"(v.x), "=f"(v.y) : "l"(acc[o][0]));
            asm("mov.b64 {%0,%1}, %2;" : "=f"(v.z), "=f"(v.w) : "l"(acc[o][1]));
            *(float4*)(dp + (size_t)o*HW) = v;
        }
    }
}

// ---------------- QKV projection ----------------
__global__ void qkv_kernel(const float* __restrict__ wq, const float* __restrict__ bq,
                           const float* __restrict__ wk, const float* __restrict__ bk,
                           const float* __restrict__ wv, const float* __restrict__ bv){
    int b = blockIdx.x;
    int m = blockIdx.y / 4;
    int ot = (blockIdx.y % 4) * 16;
    const float* W  = (m == 0) ? wq : (m == 1 ? wk : wv);
    const float* Bb = (m == 0) ? bq : (m == 1 ? bk : bv);
    float* dst = (m == 0) ? g_q : (m == 1 ? g_k : g_v);
    __shared__ float s_w[16*64];
    int tid = threadIdx.x;
    for(int p = tid; p < 1024; p += 256) s_w[p] = W[(ot + p/64)*64 + p%64];
    __syncthreads();
    int i = tid;
    float acc[16];
    #pragma unroll
    for(int o = 0; o < 16; o++) acc[o] = Bb[ot + o];
    const float* xb = g_feat + (size_t)b*16384;
    for(int c = 0; c < 64; c++){
        float xv = xb[c*256 + i];
        #pragma unroll
        for(int o = 0; o < 16; o++) acc[o] += s_w[o*64 + c]*xv;
    }
    #pragma unroll
    for(int o = 0; o < 16; o++) dst[(size_t)b*16384 + (ot+o)*256 + i] = acc[o];
}

// ---------------- attention ----------------
__global__ void attn_kernel(const float* __restrict__ rel_h, const float* __restrict__ rel_w){
    int b = blockIdx.x, h = blockIdx.y;
    __shared__ float s_q[16*256];
    __shared__ float s_k[16*256];
    __shared__ float s_v[16*256];
    int tid = threadIdx.x;
    const size_t base = (size_t)b*16384 + h*4096;
    for(int p = tid; p < 4096; p += 256){
        s_q[p] = g_q[base + p];
        s_k[p] = g_k[base + p];
        s_v[p] = g_v[base + p];
    }
    __syncthreads();
    int warp = tid / 32, lane = tid % 32;
    for(int r = 0; r < 32; r++){
        int i = warp*32 + r;
        int a = i / 16, bcol = i % 16;
        float qi[16], pi[16];
        #pragma unroll
        for(int d = 0; d < 16; d++){
            qi[d] = s_q[d*256 + i];
            pi[d] = rel_h[(h*16 + d)*16 + bcol] + rel_w[(h*16 + d)*16 + a];
        }
        float sc[8];
        #pragma unroll
        for(int jj = 0; jj < 8; jj++){
            int j = lane + jj*32;
            float s = 0.f;
            #pragma unroll
            for(int d = 0; d < 16; d++)
                s += qi[d]*s_k[d*256 + j] + pi[d]*s_q[d*256 + j];
            sc[jj] = s;
        }
        float mx = sc[0];
        #pragma unroll
        for(int jj = 1; jj < 8; jj++) mx = fmaxf(mx, sc[jj]);
        #pragma unroll
        for(int o = 16; o > 0; o >>= 1) mx = fmaxf(mx, __shfl_xor_sync(0xffffffffu, mx, o));
        float sum = 0.f;
        #pragma unroll
        for(int jj = 0; jj < 8; jj++){ sc[jj] = __expf(sc[jj] - mx); sum += sc[jj]; }
        #pragma unroll
        for(int o = 16; o > 0; o >>= 1) sum += __shfl_xor_sync(0xffffffffu, sum, o);
        float inv = 1.f / sum;
        #pragma unroll
        for(int d = 0; d < 16; d++){
            float pv = 0.f;
            #pragma unroll
            for(int jj = 0; jj < 8; jj++) pv += s_v[d*256 + lane + jj*32]*sc[jj];
            #pragma unroll
            for(int o = 16; o > 0; o >>= 1) pv += __shfl_xor_sync(0xffffffffu, pv, o);
            if(lane == 0) g_att[base + d*256 + i] = pv*inv;
        }
    }
}

// ---------------- per-sample LayerNorm + residual (fp32) ----------------
__global__ void ln_kernel(const float* __restrict__ ln_g, const float* __restrict__ ln_b){
    int b = blockIdx.x, tid = threadIdx.x;
    const float* src = g_att + (size_t)b*16384;
    float s = 0.f, s2 = 0.f;
    for(int p = tid; p < 4096; p += 256){
        float4 v = *(const float4*)&src[p*4];
        s  += (v.x + v.y) + (v.z + v.w);
        s2 += v.x*v.x + v.y*v.y + v.z*v.z + v.w*v.w;
    }
    __shared__ float sh[256], sh2[256];
    sh[tid] = s; sh2[tid] = s2; __syncthreads();
    for(int o = 128; o > 0; o >>= 1){
        if(tid < o){ sh[tid] += sh[tid+o]; sh2[tid] += sh2[tid+o]; }
        __syncthreads();
    }
    __shared__ float m_s, r_s;
    if(tid == 0){
        double m = (double)sh[0]/16384.0;
        double var = (double)sh2[0]/16384.0 - m*m;
        m_s = (float)m;
        r_s = (float)(1.0/sqrt(var + 1e-5));
    }
    __syncthreads();
    float m = m_s, r = r_s;
    for(int p = tid; p < 16384; p += 256){
        g_mh[(size_t)b*16384 + p] = (src[p] - m)*r*ln_g[p] + ln_b[p] + g_feat[(size_t)b*16384 + p];
    }
}

// ---------------- CBAM channel attention ----------------
__global__ void ca_kernel(const float* __restrict__ w1, const float* __restrict__ b1,
                          const float* __restrict__ w2, const float* __restrict__ b2){
    int b = blockIdx.x, tid = threadIdx.x;
    __shared__ float s_sum[256], s_max[256];
    int c = tid / 4, qp = tid % 4;
    const float* p = g_feat + (size_t)(b*64 + c)*256 + qp*64;
    float s = 0.f, mx = -1e30f;
    for(int i = 0; i < 64; i++){ float v = p[i]; s += v; mx = fmaxf(mx, v); }
    s_sum[tid] = s; s_max[tid] = mx;
    __syncthreads();
    __shared__ float avg[64], mxc[64];
    if(tid < 64){
        float ss = 0.f, mm = -1e30f;
        for(int q = 0; q < 4; q++){ ss += s_sum[tid*4+q]; mm = fmaxf(mm, s_max[tid*4+q]); }
        avg[tid] = ss/256.f; mxc[tid] = mm;
    }
    __syncthreads();
    __shared__ float hA[4], hM[4];
    if(tid < 8){
        int hh = tid % 4; bool isA = tid < 4;
        const float* f = isA ? avg : mxc;
        float a = b1[hh];
        for(int cc = 0; cc < 64; cc++) a += w1[hh*64 + cc]*f[cc];
        a = fmaxf(a, 0.f);
        if(isA) hA[hh] = a; else hM[hh] = a;
    }
    __syncthreads();
    if(tid < 64){
        float sv = 2.f*b2[tid];
        for(int hh = 0; hh < 4; hh++) sv += w2[tid*4 + hh]*(hA[hh] + hM[hh]);
        g_scale[b*64 + tid] = 1.f/(1.f + __expf(-sv));
    }
}

// ---------------- CBAM spatial features ----------------
__global__ void sf_kernel(){
    int b = blockIdx.x, i = threadIdx.x;
    float s = 0.f, mx = -1e30f;
    for(int c = 0; c < 64; c++){
        float v = g_scale[b*64 + c]*g_feat[(size_t)b*16384 + c*256 + i];
        s += v; mx = fmaxf(mx, v);
    }
    g_sf[b*512 + i] = s/64.f;
    g_sf[b*512 + 256 + i] = mx;
}

// ---------------- 7x7 spatial attention conv + sigmoid ----------------
__global__ void saconv_kernel(const float* __restrict__ sw, const float* __restrict__ sb){
    int b = blockIdx.x, i = threadIdx.x;
    int y = i/16, x = i%16;
    float a = sb[0];
    for(int ch = 0; ch < 2; ch++)
        for(int ky = 0; ky < 7; ky++){
            int yy = y + ky - 3; if(yy < 0 || yy >= 16) continue;
            for(int kx = 0; kx < 7; kx++){
                int xx = x + kx - 3; if(xx < 0 || xx >= 16) continue;
                a += sw[ch*49 + ky*7 + kx]*g_sf[b*512 + ch*256 + yy*16 + xx];
            }
        }
    g_sa[b*256 + i] = 1.f/(1.f + __expf(-a));
}

// ---------------- final combine ----------------
__global__ void comb_kernel(){
    int idx = blockIdx.x*256 + threadIdx.x;
    if(idx >= NIMG*16384) return;
    int b = idx/16384, rr = idx%16384, c = rr/256, i = rr%256;
    float xv = g_feat[idx];
    g_y[idx] = g_mh[idx] + g_sa[b*256 + i]*g_scale[b*64 + c]*xv + xv;
}

// ---------------- covariance pipeline ----------------
__global__ void cmean_kernel(){
    int n = blockIdx.x/64, c = blockIdx.x%64, tid = threadIdx.x;
    float s = 0.f;
    for(int m = tid; m < 1280; m += 256){
        int im = 64 + n*5 + m/256, i = m%256;
        s += g_y[(size_t)(im*64 + c)*256 + i];
    }
    __shared__ float sh[256];
    sh[tid] = s; __syncthreads();
    for(int o = 128; o > 0; o >>= 1){ if(tid < o) sh[tid] += sh[tid+o]; __syncthreads(); }
    if(tid == 0) g_cmean[n*64 + c] = sh[0]/1280.f;
}

__global__ void xc_kernel(){
    int idx = blockIdx.x*256 + threadIdx.x;
    if(idx >= 5*64*1280) return;
    int n = idx/(64*1280), rr = idx%(64*1280), c = rr/1280, m = rr%1280;
    int im = 64 + n*5 + m/256, i = m%256;
    g_xc[idx] = g_y[(size_t)(im*64 + c)*256 + i] - g_cmean[n*64 + c];
}

__global__ void cov_kernel(){
    int n = blockIdx.x;
    int pid = blockIdx.y*256 + threadIdx.x;
    int c = pid/64, d = pid%64;
    const float4* a  = (const float4*)(g_xc + (size_t)(n*64 + c)*1280);
    const float4* bb = (const float4*)(g_xc + (size_t)(n*64 + d)*1280);
    float s = 0.f;
    #pragma unroll 4
    for(int m = 0; m < 320; m++){
        float4 av = a[m], bv = bb[m];
        s += av.x*bv.x + av.y*bv.y + av.z*bv.z + av.w*bv.w;
    }
    g_cov[n*4096 + pid] = s/1279.f;
}

// ---------------- query normalization + transpose ----------------
__global__ void qn_kernel(){
    int b = blockIdx.x, tid = threadIdx.x;
    __shared__ float part[256];
    __shared__ float rn[64];
    int c = tid/4, qp = tid%4;
    const float* p = g_y + (size_t)(b*64 + c)*256 + qp*64;
    float s = 0.f;
    for(int i = 0; i < 64; i++) s += p[i]*p[i];
    part[tid] = s; __syncthreads();
    if(tid < 64){
        float t = part[tid*4] + part[tid*4+1] + part[tid*4+2] + part[tid*4+3];
        rn[tid] = 1.f/sqrtf(t);
    }
    __syncthreads();
    for(int p2 = tid; p2 < 16384; p2 += 256){
        int c2 = p2/256, i = p2%256;
        g_qn[(size_t)(b*256 + i)*64 + c2] = g_y[(size_t)(b*64 + c2)*256 + i]*rn[c2];
    }
}

// ---------------- sim quadratic form + classifier ----------------
__global__ void sim_kernel(const float* __restrict__ cls_w, float* __restrict__ out){
    int b = blockIdx.x, j = blockIdx.y;
    __shared__ float s_cov[4096];
    int tid = threadIdx.x;
    for(int p = tid; p < 4096; p += 256) s_cov[p] = g_cov[j*4096 + p];
    __syncthreads();
    float v[64];
    const float4* vp = (const float4*)(g_qn + (size_t)(b*256 + tid)*64);
    #pragma unroll
    for(int c4 = 0; c4 < 16; c4++){
        float4 f = vp[c4];
        v[c4*4] = f.x; v[c4*4+1] = f.y; v[c4*4+2] = f.z; v[c4*4+3] = f.w;
    }
    float quad = 0.f;
    for(int c = 0; c < 64; c++){
        float t = 0.f;
        #pragma unroll 8
        for(int d = 0; d < 64; d++) t += s_cov[c*64 + d]*v[d];
        quad += v[c]*t;
    }
    float val = quad >= 0.f ? quad : NEG*quad;
    val *= cls_w[tid];
    __shared__ float red[256];
    red[tid] = val; __syncthreads();
    for(int o = 128; o > 0; o >>= 1){ if(tid < o) red[tid] += red[tid+o]; __syncthreads(); }
    if(tid == 0) out[b*5 + j] = red[0];
}

// ---------------- host orchestration ----------------
extern "C" void kernel_launch(void* const* d_in, const int* in_sizes, int n_in,
                              void* d_out, int out_size){
    const float* input1  = (const float*)d_in[0];
    const float* input2  = (const float*)d_in[1];
    const float* conv1_w = (const float*)d_in[2];
    const float* bn1_g = (const float*)d_in[3];  const float* bn1_b = (const float*)d_in[4];
    const float* conv2_w = (const float*)d_in[5];
    const float* bn2_g = (const float*)d_in[6];  const float* bn2_b = (const float*)d_in[7];
    const float* conv3_w = (const float*)d_in[8];
    const float* bn3_g = (const float*)d_in[9];  const float* bn3_b = (const float*)d_in[10];
    const float* conv4_w = (const float*)d_in[11];
    const float* bn4_g = (const float*)d_in[12]; const float* bn4_b = (const float*)d_in[13];
    const float* wq = (const float*)d_in[14]; const float* bq = (const float*)d_in[15];
    const float* wk = (const float*)d_in[16]; const float* bk = (const float*)d_in[17];
    const float* wv = (const float*)d_in[18]; const float* bv = (const float*)d_in[19];
    const float* rel_h = (const float*)d_in[20]; const float* rel_w = (const float*)d_in[21];
    const float* ln_g = (const float*)d_in[22];  const float* ln_b = (const float*)d_in[23];
    const float* ca_w1 = (const float*)d_in[24]; const float* ca_b1 = (const float*)d_in[25];
    const float* ca_w2 = (const float*)d_in[26]; const float* ca_b2 = (const float*)d_in[27];
    const float* sa_w = (const float*)d_in[28];  const float* sa_b = (const float*)d_in[29];
    const float* cls_w = (const float*)d_in[30];
    float* out = (float*)d_out;

    float *p_conv1, *p_pool1, *p_conv2, *p_pool2, *p_conv3, *p_a3, *p_conv4, *p_feat;
    cudaGetSymbolAddress((void**)&p_conv1, g_conv1);
    cudaGetSymbolAddress((void**)&p_pool1, g_pool1);
    cudaGetSymbolAddress((void**)&p_conv2, g_conv2);
    cudaGetSymbolAddress((void**)&p_pool2, g_pool2);
    cudaGetSymbolAddress((void**)&p_conv3, g_conv3);
    cudaGetSymbolAddress((void**)&p_a3,    g_a3);
    cudaGetSymbolAddress((void**)&p_conv4, g_conv4);
    cudaGetSymbolAddress((void**)&p_feat,  g_feat);

    // conv64 smem sizes
    const int smem32 = 16*64*9*8 + 2*1*(34*36)*4;   // 73728 + 9792 = 83520
    const int smem16 = 8*64*9*8 + 2*2*(18*20)*4;    // 36864 + 5760 = 42624
    cudaFuncSetAttribute((const void*)conv64v2_kernel<32,16,1>,
                         cudaFuncAttributeMaxDynamicSharedMemorySize, smem32);
    cudaFuncSetAttribute((const void*)conv64v2_kernel<16,8,2>,
                         cudaFuncAttributeMaxDynamicSharedMemorySize, smem16);

    // features
    conv1_kernel<<<dim3(NIMG,8),256>>>(input1, input2, conv1_w);
    bnstats_kernel<<<384,256>>>(p_conv1, 4096, 0);
    bn_pool_kernel<<<(NIMG*64*1024+255)/256,256>>>(p_conv1, p_pool1, 32, 0, bn1_g, bn1_b);

    conv64v2_kernel<32,16,1><<<dim3(NIMG,4),256,smem32>>>(p_pool1, conv2_w, p_conv2);
    bnstats_kernel<<<384,256>>>(p_conv2, 1024, 1);
    bn_pool_kernel<<<(NIMG*64*256+255)/256,256>>>(p_conv2, p_pool2, 16, 1, bn2_g, bn2_b);

    conv64v2_kernel<16,8,2><<<dim3((NIMG+1)/2,8),128,smem16>>>(p_pool2, conv3_w, p_conv3);
    bnstats_kernel<<<384,256>>>(p_conv3, 256, 2);
    bn_act_kernel<<<(NIMG*64*256+255)/256,256>>>(p_conv3, p_a3, 256, 2, bn3_g, bn3_b);

    conv64v2_kernel<16,8,2><<<dim3((NIMG+1)/2,8),128,smem16>>>(p_a3, conv4_w, p_conv4);
    bnstats_kernel<<<384,256>>>(p_conv4, 256, 3);
    bn_act_kernel<<<(NIMG*64*256+255)/256,256>>>(p_conv4, p_feat, 256, 3, bn4_g, bn4_b);

    // sa_module
    qkv_kernel<<<dim3(NIMG,12),256>>>(wq, bq, wk, bk, wv, bv);
    attn_kernel<<<dim3(NIMG,4),256>>>(rel_h, rel_w);
    ln_kernel<<<NIMG,256>>>(ln_g, ln_b);
    ca_kernel<<<NIMG,256>>>(ca_w1, ca_b1, ca_w2, ca_b2);
    sf_kernel<<<NIMG,256>>>();
    saconv_kernel<<<NIMG,256>>>(sa_w, sa_b);
    comb_kernel<<<(NIMG*16384+255)/256,256>>>();

    // covariance + similarity
    cmean_kernel<<<320,256>>>();
    xc_kernel<<<(5*64*1280+255)/256,256>>>();
    cov_kernel<<<dim3(5,16),256>>>();
    qn_kernel<<<64,256>>>();
    sim_kernel<<<dim3(64,5),256>>>(cls_w, out);
}